// round 12
// baseline (speedup 1.0000x reference)
#include <cuda_runtime.h>
#include <cuda_bf16.h>
#include <cstdint>

#define B_  2
#define S_  2048
#define H_  2048
#define NH_ 16
#define HD_ 128
#define M_  (B_*S_)            // 4096
#define SCALE_ 0.08838834764831845f   // 128^-0.5
#define LOG2E_ 1.4426950408889634f

// ---------------- scratch (device globals: no allocation allowed) ----------
__device__ float g_q[(size_t)B_*NH_*S_*HD_];     // [b,h,s,d] fp32
__device__ float g_k[(size_t)B_*NH_*S_*HD_];     // [b,h,s,d] tf32 bits (post-rope)
__device__ float g_v[(size_t)B_*NH_*S_*HD_];     // [b,h,s,d] tf32 bits
__device__ float g_ctx[(size_t)B_*S_*H_];        // [b,s,h*HD+d] tf32 bits
__device__ float g_xc[(size_t)M_*H_];            // X  pre-rounded to tf32
__device__ float g_wq[(size_t)H_*H_];            // W* pre-rounded to tf32
__device__ float g_wk[(size_t)H_*H_];
__device__ float g_wv[(size_t)H_*H_];
__device__ float g_wo[(size_t)H_*H_];

// ---------------- tf32 helpers ---------------------------------------------
__device__ __forceinline__ unsigned tf32_of(float f) {
    unsigned r; asm("cvt.rn.tf32.f32 %0, %1;" : "=r"(r) : "f"(f)); return r;
}
__device__ __forceinline__ uint4 cvt4(float4 v) {
    uint4 o; o.x = tf32_of(v.x); o.y = tf32_of(v.y); o.z = tf32_of(v.z); o.w = tf32_of(v.w);
    return o;
}
__device__ __forceinline__ float ex2(float x) {
    float r; asm("ex2.approx.ftz.f32 %0, %1;" : "=f"(r) : "f"(x)); return r;
}
__device__ __forceinline__ void mma8(float* c, const unsigned* a, unsigned b0, unsigned b1) {
    asm volatile(
        "mma.sync.aligned.m16n8k8.row.col.f32.tf32.tf32.f32 "
        "{%0,%1,%2,%3}, {%4,%5,%6,%7}, {%8,%9}, {%0,%1,%2,%3};"
        : "+f"(c[0]), "+f"(c[1]), "+f"(c[2]), "+f"(c[3])
        : "r"(a[0]), "r"(a[1]), "r"(a[2]), "r"(a[3]), "r"(b0), "r"(b1));
}
__device__ __forceinline__ uint32_t smem_u32(const void* p) {
    uint32_t a;
    asm("{ .reg .u64 t; cvta.to.shared.u64 t, %1; cvt.u32.u64 %0, t; }" : "=r"(a) : "l"(p));
    return a;
}
__device__ __forceinline__ void cp16(uint32_t saddr, const float* g) {
    asm volatile("cp.async.cg.shared.global [%0], [%1], 16;" :: "r"(saddr), "l"(g) : "memory");
}
#define CP_COMMIT() asm volatile("cp.async.commit_group;" ::: "memory")
#define CP_WAIT2()  asm volatile("cp.async.wait_group 2;" ::: "memory")
#define CP_WAIT0()  asm volatile("cp.async.wait_group 0;" ::: "memory")

// ---------------- pre-conversion kernels -----------------------------------
__global__ void k_cvt(const float* __restrict__ src, float* __restrict__ dst) {
    int i = blockIdx.x * blockDim.x + threadIdx.x;
    float4 v = ((const float4*)src)[i];
    ((uint4*)dst)[i] = cvt4(v);
}
__global__ void k_cvtw(const float* __restrict__ Wq, const float* __restrict__ Wk,
                       const float* __restrict__ Wv, const float* __restrict__ Wo) {
    int i = blockIdx.x * blockDim.x + threadIdx.x;
    const float* src = (blockIdx.y == 0) ? Wq : (blockIdx.y == 1) ? Wk
                     : (blockIdx.y == 2) ? Wv : Wo;
    float* dst = (blockIdx.y == 0) ? g_wq : (blockIdx.y == 1) ? g_wk
               : (blockIdx.y == 2) ? g_wv : g_wo;
    float4 v = ((const float4*)src)[i];
    ((uint4*)dst)[i] = cvt4(v);
}

// ======================= tf32 mma.sync GEMM ================================
// CTA 128x128, GK=16, 512 thr, 16 warps as 4(m)x4(n); warp tile 32x32
// (mf=2, nf=4, 32 accum regs). Scalar-LDS fragments, 4 cp.async stages,
// 64KB smem. __launch_bounds__(512,2): 2 CTAs/SM = 32 warps = 8/SMSP.
#define GM 128
#define GN 128
#define GK 16
#define NST 4
#define STAGE_W ((GM + GN) * GK)                  // floats per stage (4096)
#define GEMM_SMEM (NST * STAGE_W * 4)             // 65536 bytes

__device__ __forceinline__ int swz(int row, int col) {     // byte offset
    int off = row * 64 + col * 4;
    return off ^ ((off >> 3) & 0x70);
}

// MODE 0: C[m*H_+n]  MODE 1: scatter [b,h,s,d] fp32  MODE 2: scatter tf32
template<int MODE>
__device__ __forceinline__ void gemm_tc(const float* __restrict__ A,
                                        const float* __restrict__ W,
                                        float* __restrict__ Cdst,
                                        int mb, int nb)
{
    extern __shared__ float gsm[];
    const uint32_t sb = smem_u32(gsm);
    const int tid = threadIdx.x;
    const int wid = tid >> 5, lane = tid & 31;
    const int g = lane >> 2, r = lane & 3;
    const int wm = (wid >> 2) * 32;      // 4 m-warp rows
    const int wn = (wid & 3) * 32;       // 4 n-warp cols

    float c[2][4][4];
#pragma unroll
    for (int i = 0; i < 2; i++)
#pragma unroll
        for (int j = 0; j < 4; j++)
#pragma unroll
            for (int e = 0; e < 4; e++) c[i][j][e] = 0.f;

    const int lrow = tid >> 2, lslot = tid & 3;          // 512 thr: rows 0..127

    auto issue = [&](int ch) {
        uint32_t st = sb + (ch & (NST - 1)) * (STAGE_W * 4);
        const float* Ab = A + (size_t)mb * H_ + ch * GK;
        const float* Wb = W + (size_t)nb * H_ + ch * GK;
        cp16(st + swz(lrow, lslot * 4), Ab + (size_t)lrow * H_ + lslot * 4);
        uint32_t stb = st + GM * GK * 4;
        cp16(stb + swz(lrow, lslot * 4), Wb + (size_t)lrow * H_ + lslot * 4);
    };

    issue(0); CP_COMMIT();
    issue(1); CP_COMMIT();
    issue(2); CP_COMMIT();

    const int NCH = H_ / GK;                             // 128
    for (int ch = 0; ch < NCH; ch++) {
        CP_WAIT2();
        __syncthreads();
        if (ch + 3 < NCH) issue(ch + 3);
        CP_COMMIT();
        const char* as = (const char*)gsm + (ch & (NST - 1)) * (STAGE_W * 4);
        const char* bs = as + GM * GK * 4;
#pragma unroll
        for (int ks = 0; ks < 2; ks++) {
            unsigned bf[4][2];
#pragma unroll
            for (int nf = 0; nf < 4; nf++) {
                int row = wn + nf * 8 + g;
                bf[nf][0] = *(const unsigned*)(bs + swz(row, ks * 8 + r));
                bf[nf][1] = *(const unsigned*)(bs + swz(row, ks * 8 + r + 4));
            }
#pragma unroll
            for (int mf = 0; mf < 2; mf++) {
                unsigned af[4];
                int row = wm + mf * 16 + g;
                af[0] = *(const unsigned*)(as + swz(row,     ks * 8 + r));
                af[1] = *(const unsigned*)(as + swz(row + 8, ks * 8 + r));
                af[2] = *(const unsigned*)(as + swz(row,     ks * 8 + r + 4));
                af[3] = *(const unsigned*)(as + swz(row + 8, ks * 8 + r + 4));
#pragma unroll
                for (int nf = 0; nf < 4; nf++)
                    mma8(c[mf][nf], af, bf[nf][0], bf[nf][1]);
            }
        }
    }

    // epilogue
#pragma unroll
    for (int mf = 0; mf < 2; mf++) {
#pragma unroll
        for (int nf = 0; nf < 4; nf++) {
            int mrow = mb + wm + mf * 16 + g;
            int col  = nb + wn + nf * 8 + r * 2;
#pragma unroll
            for (int half = 0; half < 2; half++) {
                int m = mrow + half * 8;
                float2 v = make_float2(c[mf][nf][half * 2], c[mf][nf][half * 2 + 1]);
                if (MODE == 0) {
                    *(float2*)&Cdst[(size_t)m * H_ + col] = v;
                } else {
                    if (MODE == 2) {
                        v.x = __uint_as_float(tf32_of(v.x));
                        v.y = __uint_as_float(tf32_of(v.y));
                    }
                    int b = m >> 11, s = m & (S_ - 1);
                    int h = col >> 7, d0 = col & (HD_ - 1);
                    *(float2*)&Cdst[(((size_t)(b * NH_ + h)) * S_ + s) * HD_ + d0] = v;
                }
            }
        }
    }
}

__global__ void __launch_bounds__(512, 2) k_qkv_tc() {
    int which = blockIdx.x >> 4;                 // 0=q 1=k 2=v
    int nb = (blockIdx.x & 15) * GN;
    int mb = blockIdx.y * GM;
    if (which == 0)      gemm_tc<1>(g_xc, g_wq, g_q, mb, nb);
    else if (which == 1) gemm_tc<1>(g_xc, g_wk, g_k, mb, nb);
    else                 gemm_tc<2>(g_xc, g_wv, g_v, mb, nb);
}
__global__ void __launch_bounds__(512, 2) k_out_tc(float* __restrict__ C) {
    gemm_tc<0>(g_ctx, g_wo, C, (int)blockIdx.y * GM, (int)blockIdx.x * GN);
}

// ---------------- RoPE (in place; K is rounded to tf32 bits) ---------------
__global__ void k_rope(const float* __restrict__ cosp, const float* __restrict__ sinp)
{
    int idx = blockIdx.x * blockDim.x + threadIdx.x;   // B*NH*S*64 threads
    int d  = idx & 63;
    int s  = (idx >> 6) & (S_ - 1);
    int bh = idx >> 17;
    size_t base = ((size_t)bh * S_ + s) * HD_;
    float c1 = cosp[s*HD_ + d],      s1 = sinp[s*HD_ + d];
    float c2 = cosp[s*HD_ + d + 64], s2 = sinp[s*HD_ + d + 64];
    float x1 = g_q[base + d], x2 = g_q[base + d + 64];
    g_q[base + d]      = x1*c1 - x2*s1;
    g_q[base + d + 64] = x2*c2 + x1*s2;
    x1 = g_k[base + d]; x2 = g_k[base + d + 64];
    g_k[base + d]      = __uint_as_float(tf32_of(x1*c1 - x2*s1));
    g_k[base + d + 64] = __uint_as_float(tf32_of(x2*c2 + x1*s2));
}

// ---------------- causal flash attention (tensor cores, cp.async) ----------
#define BQ   128
#define BKT  64
#define NQT  (S_/BQ)                      // 16
#define STRK 132
#define STRV 136
#define STRP 68
#define KVW  (64*STRK + 64*STRV)          // floats per K+V buffer = 17152
#define PS_OFF (2*KVW)                    // 34304
#define FLASH_SMEM_BYTES ((PS_OFF + 8*16*STRP)*4)   // 172032

__global__ void __launch_bounds__(256, 1) k_flash_tc()
{
    extern __shared__ float fsm[];
    const uint32_t fsb = smem_u32(fsm);
    const int tid = threadIdx.x;
    const int wid = tid >> 5, lane = tid & 31;
    const int g = lane >> 2, r = lane & 3;
    const int qt = (NQT - 1) - (int)blockIdx.x;      // longest tiles first
    const int bh = blockIdx.y;
    const int b = bh >> 4, h = bh & (NH_ - 1);
    const size_t base = (size_t)bh * S_ * HD_;
    const int qrow0 = qt*BQ + wid*16;

    unsigned qa[16][4];
    {
        const float* qp = g_q + base + (size_t)qrow0 * HD_;
        const float qs = SCALE_ * LOG2E_;           // log2-domain scores
#pragma unroll
        for (int ks = 0; ks < 16; ks++) {
            qa[ks][0] = tf32_of(qp[(size_t)g*HD_     + ks*8 + r    ] * qs);
            qa[ks][1] = tf32_of(qp[(size_t)(g+8)*HD_ + ks*8 + r    ] * qs);
            qa[ks][2] = tf32_of(qp[(size_t)g*HD_     + ks*8 + r + 4] * qs);
            qa[ks][3] = tf32_of(qp[(size_t)(g+8)*HD_ + ks*8 + r + 4] * qs);
        }
    }

    float oc[16][4];
#pragma unroll
    for (int nf = 0; nf < 16; nf++)
#pragma unroll
        for (int e = 0; e < 4; e++) oc[nf][e] = 0.f;
    float m0 = -1e30f, m1 = -1e30f, l0 = 0.f, l1 = 0.f;

    float* Pw = fsm + PS_OFF + wid * (16*STRP);
    const int ntiles = 2*(qt + 1);

    auto stage = [&](int kt2, int buf) {
        const float* kp = g_k + base + (size_t)kt2*BKT*HD_;
        const float* vp = g_v + base + (size_t)kt2*BKT*HD_;
        uint32_t ks_ = fsb + (uint32_t)buf * (KVW*4);
        uint32_t vs_ = ks_ + 64*STRK*4;
#pragma unroll
        for (int it = 0; it < 8; it++) {
            int f = tid + 256*it;            // 0..2047
            int row = f >> 5, c4 = (f & 31) * 4;
            cp16(ks_ + (row*STRK + c4)*4, kp + row*HD_ + c4);
            cp16(vs_ + (row*STRV + c4)*4, vp + row*HD_ + c4);
        }
    };

    stage(0, 0); CP_COMMIT();

    for (int kt = 0; kt < ntiles; kt++) {
        CP_WAIT0();
        __syncthreads();
        if (kt + 1 < ntiles) { stage(kt + 1, (kt + 1) & 1); CP_COMMIT(); }
        const float* Ks = fsm + (kt & 1) * KVW;
        const float* Vs = Ks + 64*STRK;

        if (kt*BKT <= qrow0 + 15) {
            float sc[8][4];
#pragma unroll
            for (int nf = 0; nf < 8; nf++)
#pragma unroll
                for (int e = 0; e < 4; e++) sc[nf][e] = 0.f;
#pragma unroll
            for (int ks = 0; ks < 16; ks++) {
#pragma unroll
                for (int nf = 0; nf < 8; nf++) {
                    unsigned b0 = __float_as_uint(Ks[(nf*8+g)*STRK + ks*8 + r]);
                    unsigned b1 = __float_as_uint(Ks[(nf*8+g)*STRK + ks*8 + r + 4]);
                    mma8(sc[nf], qa[ks], b0, b1);
                }
            }
            if (kt*BKT + BKT - 1 > qrow0) {
#pragma unroll
                for (int nf = 0; nf < 8; nf++) {
                    int key0 = kt*BKT + nf*8 + 2*r;
                    if (key0     > qrow0 + g)     sc[nf][0] = -1e30f;
                    if (key0 + 1 > qrow0 + g)     sc[nf][1] = -1e30f;
                    if (key0     > qrow0 + g + 8) sc[nf][2] = -1e30f;
                    if (key0 + 1 > qrow0 + g + 8) sc[nf][3] = -1e30f;
                }
            }
            float mx0 = sc[0][0], mx1 = sc[0][2];
#pragma unroll
            for (int nf = 0; nf < 8; nf++) {
                mx0 = fmaxf(mx0, fmaxf(sc[nf][0], sc[nf][1]));
                mx1 = fmaxf(mx1, fmaxf(sc[nf][2], sc[nf][3]));
            }
            mx0 = fmaxf(mx0, __shfl_xor_sync(0xffffffffu, mx0, 1));
            mx0 = fmaxf(mx0, __shfl_xor_sync(0xffffffffu, mx0, 2));
            mx1 = fmaxf(mx1, __shfl_xor_sync(0xffffffffu, mx1, 1));
            mx1 = fmaxf(mx1, __shfl_xor_sync(0xffffffffu, mx1, 2));
            float mn0 = fmaxf(m0, mx0), mn1 = fmaxf(m1, mx1);
            float cr0 = ex2(m0 - mn0), cr1 = ex2(m1 - mn1);
            m0 = mn0; m1 = mn1;
            l0 *= cr0; l1 *= cr1;
#pragma unroll
            for (int nf = 0; nf < 16; nf++) {
                oc[nf][0] *= cr0; oc[nf][1] *= cr0;
                oc[nf][2] *= cr1; oc[nf][3] *= cr1;
            }
#pragma unroll
            for (int nf = 0; nf < 8; nf++) {
                float p0 = ex2(sc[nf][0] - mn0);
                float p1 = ex2(sc[nf][1] - mn0);
                float p2 = ex2(sc[nf][2] - mn1);
                float p3 = ex2(sc[nf][3] - mn1);
                l0 += p0 + p1; l1 += p2 + p3;
                *(uint2*)&Pw[g*STRP     + nf*8 + 2*r] = make_uint2(tf32_of(p0), tf32_of(p1));
                *(uint2*)&Pw[(g+8)*STRP + nf*8 + 2*r] = make_uint2(tf32_of(p2), tf32_of(p3));
            }
            __syncwarp();
#pragma unroll
            for (int ks = 0; ks < 8; ks++) {
                unsigned pa[4];
                pa[0] = __float_as_uint(Pw[g*STRP     + ks*8 + r]);
                pa[1] = __float_as_uint(Pw[(g+8)*STRP + ks*8 + r]);
                pa[2] = __float_as_uint(Pw[g*STRP     + ks*8 + r + 4]);
                pa[3] = __float_as_uint(Pw[(g+8)*STRP + ks*8 + r + 4]);
#pragma unroll
                for (int nf = 0; nf < 16; nf++) {
                    unsigned b0 = __float_as_uint(Vs[(ks*8+r)*STRV   + nf*8 + g]);
                    unsigned b1 = __float_as_uint(Vs[(ks*8+r+4)*STRV + nf*8 + g]);
                    mma8(oc[nf], pa, b0, b1);
                }
            }
            __syncwarp();
        }
    }

    l0 += __shfl_xor_sync(0xffffffffu, l0, 1);
    l0 += __shfl_xor_sync(0xffffffffu, l0, 2);
    l1 += __shfl_xor_sync(0xffffffffu, l1, 1);
    l1 += __shfl_xor_sync(0xffffffffu, l1, 2);
    float i0 = 1.f / l0, i1 = 1.f / l1;
    float* o0 = g_ctx + ((size_t)b*S_ + qrow0 + g    ) * H_ + h*HD_;
    float* o1 = g_ctx + ((size_t)b*S_ + qrow0 + g + 8) * H_ + h*HD_;
#pragma unroll
    for (int nf = 0; nf < 16; nf++) {
        *(uint2*)&o0[nf*8 + 2*r] = make_uint2(tf32_of(oc[nf][0]*i0), tf32_of(oc[nf][1]*i0));
        *(uint2*)&o1[nf*8 + 2*r] = make_uint2(tf32_of(oc[nf][2]*i1), tf32_of(oc[nf][3]*i1));
    }
}

// ---------------- launch ---------------------------------------------------
extern "C" void kernel_launch(void* const* d_in, const int* in_sizes, int n_in,
                              void* d_out, int out_size)
{
    const float* X   = (const float*)d_in[0];
    const float* cp  = (const float*)d_in[1];
    const float* sp  = (const float*)d_in[2];
    const float* Wq  = (const float*)d_in[3];
    const float* Wk  = (const float*)d_in[4];
    const float* Wv  = (const float*)d_in[5];
    const float* Wo  = (const float*)d_in[6];
    float* out = (float*)d_out;

    cudaFuncSetAttribute(k_flash_tc, cudaFuncAttributeMaxDynamicSharedMemorySize,
                         FLASH_SMEM_BYTES);
    cudaFuncSetAttribute(k_qkv_tc, cudaFuncAttributeMaxDynamicSharedMemorySize,
                         GEMM_SMEM);
    cudaFuncSetAttribute(k_out_tc, cudaFuncAttributeMaxDynamicSharedMemorySize,
                         GEMM_SMEM);

    float* g_xc_p;
    cudaGetSymbolAddress((void**)&g_xc_p, g_xc);

    k_cvt<<<(M_*H_/4)/256, 256>>>(X, g_xc_p);
    k_cvtw<<<dim3((H_*H_/4)/256, 4), 256>>>(Wq, Wk, Wv, Wo);

    k_qkv_tc<<<dim3(48, M_/GM), 512, GEMM_SMEM>>>();

    int total = B_ * NH_ * S_ * 64;        // 4,194,304
    k_rope<<<total / 256, 256>>>(cp, sp);

    k_flash_tc<<<dim3(NQT, B_*NH_), 256, FLASH_SMEM_BYTES>>>();

    k_out_tc<<<dim3(H_/GN, M_/GM), 512, GEMM_SMEM>>>(out);
}

// round 13
// speedup vs baseline: 1.2472x; 1.2472x over previous
#include <cuda_runtime.h>
#include <cuda_bf16.h>
#include <cstdint>

#define B_  2
#define S_  2048
#define H_  2048
#define NH_ 16
#define HD_ 128
#define M_  (B_*S_)            // 4096
#define SCALE_ 0.08838834764831845f   // 128^-0.5
#define LOG2E_ 1.4426950408889634f

// ---------------- scratch (device globals: no allocation allowed) ----------
__device__ float g_q[(size_t)B_*NH_*S_*HD_];     // [b,h,s,d] fp32
__device__ float g_k[(size_t)B_*NH_*S_*HD_];     // [b,h,s,d] tf32 bits (post-rope)
__device__ float g_v[(size_t)B_*NH_*S_*HD_];     // [b,h,s,d] tf32 bits
__device__ float g_ctx[(size_t)B_*S_*H_];        // [b,s,h*HD+d] tf32 bits
__device__ float g_xc[(size_t)M_*H_];            // X  pre-rounded to tf32
__device__ float g_wq[(size_t)H_*H_];            // W* pre-rounded to tf32
__device__ float g_wk[(size_t)H_*H_];
__device__ float g_wv[(size_t)H_*H_];
__device__ float g_wo[(size_t)H_*H_];

// ---------------- tf32 helpers ---------------------------------------------
__device__ __forceinline__ unsigned tf32_of(float f) {
    unsigned r; asm("cvt.rn.tf32.f32 %0, %1;" : "=r"(r) : "f"(f)); return r;
}
__device__ __forceinline__ uint4 cvt4(float4 v) {
    uint4 o; o.x = tf32_of(v.x); o.y = tf32_of(v.y); o.z = tf32_of(v.z); o.w = tf32_of(v.w);
    return o;
}
__device__ __forceinline__ float ex2(float x) {
    float r; asm("ex2.approx.ftz.f32 %0, %1;" : "=f"(r) : "f"(x)); return r;
}
__device__ __forceinline__ void mma8(float* c, const unsigned* a, unsigned b0, unsigned b1) {
    asm volatile(
        "mma.sync.aligned.m16n8k8.row.col.f32.tf32.tf32.f32 "
        "{%0,%1,%2,%3}, {%4,%5,%6,%7}, {%8,%9}, {%0,%1,%2,%3};"
        : "+f"(c[0]), "+f"(c[1]), "+f"(c[2]), "+f"(c[3])
        : "r"(a[0]), "r"(a[1]), "r"(a[2]), "r"(a[3]), "r"(b0), "r"(b1));
}
__device__ __forceinline__ uint32_t smem_u32(const void* p) {
    uint32_t a;
    asm("{ .reg .u64 t; cvta.to.shared.u64 t, %1; cvt.u32.u64 %0, t; }" : "=r"(a) : "l"(p));
    return a;
}
__device__ __forceinline__ void cp16(uint32_t saddr, const float* g) {
    asm volatile("cp.async.cg.shared.global [%0], [%1], 16;" :: "r"(saddr), "l"(g) : "memory");
}
#define CP_COMMIT() asm volatile("cp.async.commit_group;" ::: "memory")
#define CP_WAIT1()  asm volatile("cp.async.wait_group 1;" ::: "memory")
#define CP_WAIT0()  asm volatile("cp.async.wait_group 0;" ::: "memory")

// ---------------- pre-conversion (one launch, 5 tensors) -------------------
// y=0: X (M_*H_ = 2M float4, all blocks).  y=1..4: W* (1M float4, half).
__global__ void k_cvt_all(const float* __restrict__ X,
                          const float* __restrict__ Wq, const float* __restrict__ Wk,
                          const float* __restrict__ Wv, const float* __restrict__ Wo) {
    int i = blockIdx.x * blockDim.x + threadIdx.x;
    int y = blockIdx.y;
    const float* src; float* dst;
    if (y == 0)      { src = X;  dst = g_xc; }
    else if (y == 1) { src = Wq; dst = g_wq; if (i >= H_*H_/4) return; }
    else if (y == 2) { src = Wk; dst = g_wk; if (i >= H_*H_/4) return; }
    else if (y == 3) { src = Wv; dst = g_wv; if (i >= H_*H_/4) return; }
    else             { src = Wo; dst = g_wo; if (i >= H_*H_/4) return; }
    float4 v = ((const float4*)src)[i];
    ((uint4*)dst)[i] = cvt4(v);
}

// ======================= tf32 mma.sync GEMM ================================
// CTA 128x128, GK=32 (128B rows, SW128 swizzle), 256 thr, 8 warps as
// 2(m)x4(n), warp tile 64x32, scalar-LDS fragments (conflict-free:
// bank = (4g + r + 8ks) mod 32 bijective). 3 cp.async stages x 32KB = 96KB
// -> 2 CTAs/SM. Halved barrier count vs GK=16.
#define GM 128
#define GN 128
#define GK 32
#define NST 3
#define A_STG (GM*GK*4)                     // 16384
#define STG   (2*A_STG)                     // 32768
#define GEMM_SMEM (NST*STG)                 // 98304

__device__ __forceinline__ int swz128(int row, int cb) {   // byte offset
    return row * 128 + (cb ^ ((row & 7) << 4));
}

// MODE 0: C[m*H_+n]  MODE 1: scatter [b,h,s,d] fp32  MODE 2: scatter tf32
template<int MODE>
__device__ __forceinline__ void gemm_tc(const float* __restrict__ A,
                                        const float* __restrict__ W,
                                        float* __restrict__ Cdst,
                                        int mb, int nb)
{
    extern __shared__ float gsm[];
    const uint32_t sb = smem_u32(gsm);
    const int tid = threadIdx.x;
    const int wid = tid >> 5, lane = tid & 31;
    const int g = lane >> 2, r = lane & 3;
    const int wm = (wid >> 2) * 64;
    const int wn = (wid & 3) * 32;

    float c[4][4][4];
#pragma unroll
    for (int i = 0; i < 4; i++)
#pragma unroll
        for (int j = 0; j < 4; j++)
#pragma unroll
            for (int e = 0; e < 4; e++) c[i][j][e] = 0.f;

    const int lrow = tid >> 3, lseg = tid & 7;         // cp.async mapping

    auto issue = [&](int ch) {
        uint32_t st = sb + (ch % NST) * STG;
        const float* Ab = A + (size_t)mb * H_ + ch * GK;
        const float* Wb = W + (size_t)nb * H_ + ch * GK;
#pragma unroll
        for (int q = 0; q < 4; q++) {                  // A: 128 rows
            int row = lrow + 32 * q;
            cp16(st + swz128(row, lseg * 16), Ab + (size_t)row * H_ + lseg * 4);
        }
        uint32_t stb = st + A_STG;
#pragma unroll
        for (int q = 0; q < 4; q++) {                  // B: 128 rows
            int row = lrow + 32 * q;
            cp16(stb + swz128(row, lseg * 16), Wb + (size_t)row * H_ + lseg * 4);
        }
    };

    issue(0); CP_COMMIT();
    issue(1); CP_COMMIT();

    const int NCH = H_ / GK;                           // 64
    for (int ch = 0; ch < NCH; ch++) {
        CP_WAIT1();
        __syncthreads();
        if (ch + 2 < NCH) issue(ch + 2);
        CP_COMMIT();
        const char* as = (const char*)gsm + (ch % NST) * STG;
        const char* bs = as + A_STG;
#pragma unroll
        for (int ks = 0; ks < 4; ks++) {
            unsigned bf[4][2];
#pragma unroll
            for (int nf = 0; nf < 4; nf++) {
                int row = wn + nf * 8 + g;
                bf[nf][0] = *(const unsigned*)(bs + swz128(row, (ks*8 + r) * 4));
                bf[nf][1] = *(const unsigned*)(bs + swz128(row, (ks*8 + r + 4) * 4));
            }
#pragma unroll
            for (int mf = 0; mf < 4; mf++) {
                unsigned af[4];
                int row = wm + mf * 16 + g;
                af[0] = *(const unsigned*)(as + swz128(row,     (ks*8 + r) * 4));
                af[1] = *(const unsigned*)(as + swz128(row + 8, (ks*8 + r) * 4));
                af[2] = *(const unsigned*)(as + swz128(row,     (ks*8 + r + 4) * 4));
                af[3] = *(const unsigned*)(as + swz128(row + 8, (ks*8 + r + 4) * 4));
#pragma unroll
                for (int nf = 0; nf < 4; nf++)
                    mma8(c[mf][nf], af, bf[nf][0], bf[nf][1]);
            }
        }
    }

    // epilogue
#pragma unroll
    for (int mf = 0; mf < 4; mf++) {
#pragma unroll
        for (int nf = 0; nf < 4; nf++) {
            int mrow = mb + wm + mf * 16 + g;
            int col  = nb + wn + nf * 8 + r * 2;
#pragma unroll
            for (int half = 0; half < 2; half++) {
                int m = mrow + half * 8;
                float2 v = make_float2(c[mf][nf][half * 2], c[mf][nf][half * 2 + 1]);
                if (MODE == 0) {
                    *(float2*)&Cdst[(size_t)m * H_ + col] = v;
                } else {
                    if (MODE == 2) {
                        v.x = __uint_as_float(tf32_of(v.x));
                        v.y = __uint_as_float(tf32_of(v.y));
                    }
                    int b = m >> 11, s = m & (S_ - 1);
                    int h = col >> 7, d0 = col & (HD_ - 1);
                    *(float2*)&Cdst[(((size_t)(b * NH_ + h)) * S_ + s) * HD_ + d0] = v;
                }
            }
        }
    }
}

__global__ void __launch_bounds__(256, 2) k_qkv_tc() {
    int which = blockIdx.x >> 4;                 // 0=q 1=k 2=v
    int nb = (blockIdx.x & 15) * GN;
    int mb = blockIdx.y * GM;
    if (which == 0)      gemm_tc<1>(g_xc, g_wq, g_q, mb, nb);
    else if (which == 1) gemm_tc<1>(g_xc, g_wk, g_k, mb, nb);
    else                 gemm_tc<2>(g_xc, g_wv, g_v, mb, nb);
}
__global__ void __launch_bounds__(256, 2) k_out_tc(float* __restrict__ C) {
    gemm_tc<0>(g_ctx, g_wo, C, (int)blockIdx.y * GM, (int)blockIdx.x * GN);
}

// ---------------- RoPE (in place; K is rounded to tf32 bits) ---------------
__global__ void k_rope(const float* __restrict__ cosp, const float* __restrict__ sinp)
{
    int idx = blockIdx.x * blockDim.x + threadIdx.x;   // B*NH*S*64 threads
    int d  = idx & 63;
    int s  = (idx >> 6) & (S_ - 1);
    int bh = idx >> 17;
    size_t base = ((size_t)bh * S_ + s) * HD_;
    float c1 = cosp[s*HD_ + d],      s1 = sinp[s*HD_ + d];
    float c2 = cosp[s*HD_ + d + 64], s2 = sinp[s*HD_ + d + 64];
    float x1 = g_q[base + d], x2 = g_q[base + d + 64];
    g_q[base + d]      = x1*c1 - x2*s1;
    g_q[base + d + 64] = x2*c2 + x1*s2;
    x1 = g_k[base + d]; x2 = g_k[base + d + 64];
    g_k[base + d]      = __uint_as_float(tf32_of(x1*c1 - x2*s1));
    g_k[base + d + 64] = __uint_as_float(tf32_of(x2*c2 + x1*s2));
}

// ---------------- causal flash attention (tensor cores, cp.async) ----------
#define BQ   128
#define BKT  64
#define NQT  (S_/BQ)                      // 16
#define STRK 132
#define STRV 136
#define STRP 68
#define KVW  (64*STRK + 64*STRV)          // floats per K+V buffer = 17152
#define PS_OFF (2*KVW)                    // 34304
#define FLASH_SMEM_BYTES ((PS_OFF + 8*16*STRP)*4)   // 172032

__global__ void __launch_bounds__(256, 1) k_flash_tc()
{
    extern __shared__ float fsm[];
    const uint32_t fsb = smem_u32(fsm);
    const int tid = threadIdx.x;
    const int wid = tid >> 5, lane = tid & 31;
    const int g = lane >> 2, r = lane & 3;
    const int qt = (NQT - 1) - (int)blockIdx.x;      // longest tiles first
    const int bh = blockIdx.y;
    const int b = bh >> 4, h = bh & (NH_ - 1);
    const size_t base = (size_t)bh * S_ * HD_;
    const int qrow0 = qt*BQ + wid*16;

    unsigned qa[16][4];
    {
        const float* qp = g_q + base + (size_t)qrow0 * HD_;
        const float qs = SCALE_ * LOG2E_;           // log2-domain scores
#pragma unroll
        for (int ks = 0; ks < 16; ks++) {
            qa[ks][0] = tf32_of(qp[(size_t)g*HD_     + ks*8 + r    ] * qs);
            qa[ks][1] = tf32_of(qp[(size_t)(g+8)*HD_ + ks*8 + r    ] * qs);
            qa[ks][2] = tf32_of(qp[(size_t)g*HD_     + ks*8 + r + 4] * qs);
            qa[ks][3] = tf32_of(qp[(size_t)(g+8)*HD_ + ks*8 + r + 4] * qs);
        }
    }

    float oc[16][4];
#pragma unroll
    for (int nf = 0; nf < 16; nf++)
#pragma unroll
        for (int e = 0; e < 4; e++) oc[nf][e] = 0.f;
    float m0 = -1e30f, m1 = -1e30f, l0 = 0.f, l1 = 0.f;

    float* Pw = fsm + PS_OFF + wid * (16*STRP);
    const int ntiles = 2*(qt + 1);

    auto stage = [&](int kt2, int buf) {
        const float* kp = g_k + base + (size_t)kt2*BKT*HD_;
        const float* vp = g_v + base + (size_t)kt2*BKT*HD_;
        uint32_t ks_ = fsb + (uint32_t)buf * (KVW*4);
        uint32_t vs_ = ks_ + 64*STRK*4;
#pragma unroll
        for (int it = 0; it < 8; it++) {
            int f = tid + 256*it;            // 0..2047
            int row = f >> 5, c4 = (f & 31) * 4;
            cp16(ks_ + (row*STRK + c4)*4, kp + row*HD_ + c4);
            cp16(vs_ + (row*STRV + c4)*4, vp + row*HD_ + c4);
        }
    };

    stage(0, 0); CP_COMMIT();

    for (int kt = 0; kt < ntiles; kt++) {
        CP_WAIT0();
        __syncthreads();
        if (kt + 1 < ntiles) { stage(kt + 1, (kt + 1) & 1); CP_COMMIT(); }
        const float* Ks = fsm + (kt & 1) * KVW;
        const float* Vs = Ks + 64*STRK;

        if (kt*BKT <= qrow0 + 15) {
            float sc[8][4];
#pragma unroll
            for (int nf = 0; nf < 8; nf++)
#pragma unroll
                for (int e = 0; e < 4; e++) sc[nf][e] = 0.f;
#pragma unroll
            for (int ks = 0; ks < 16; ks++) {
#pragma unroll
                for (int nf = 0; nf < 8; nf++) {
                    unsigned b0 = __float_as_uint(Ks[(nf*8+g)*STRK + ks*8 + r]);
                    unsigned b1 = __float_as_uint(Ks[(nf*8+g)*STRK + ks*8 + r + 4]);
                    mma8(sc[nf], qa[ks], b0, b1);
                }
            }
            if (kt*BKT + BKT - 1 > qrow0) {
#pragma unroll
                for (int nf = 0; nf < 8; nf++) {
                    int key0 = kt*BKT + nf*8 + 2*r;
                    if (key0     > qrow0 + g)     sc[nf][0] = -1e30f;
                    if (key0 + 1 > qrow0 + g)     sc[nf][1] = -1e30f;
                    if (key0     > qrow0 + g + 8) sc[nf][2] = -1e30f;
                    if (key0 + 1 > qrow0 + g + 8) sc[nf][3] = -1e30f;
                }
            }
            float mx0 = sc[0][0], mx1 = sc[0][2];
#pragma unroll
            for (int nf = 0; nf < 8; nf++) {
                mx0 = fmaxf(mx0, fmaxf(sc[nf][0], sc[nf][1]));
                mx1 = fmaxf(mx1, fmaxf(sc[nf][2], sc[nf][3]));
            }
            mx0 = fmaxf(mx0, __shfl_xor_sync(0xffffffffu, mx0, 1));
            mx0 = fmaxf(mx0, __shfl_xor_sync(0xffffffffu, mx0, 2));
            mx1 = fmaxf(mx1, __shfl_xor_sync(0xffffffffu, mx1, 1));
            mx1 = fmaxf(mx1, __shfl_xor_sync(0xffffffffu, mx1, 2));
            float mn0 = fmaxf(m0, mx0), mn1 = fmaxf(m1, mx1);
            float cr0 = ex2(m0 - mn0), cr1 = ex2(m1 - mn1);
            m0 = mn0; m1 = mn1;
            l0 *= cr0; l1 *= cr1;
#pragma unroll
            for (int nf = 0; nf < 16; nf++) {
                oc[nf][0] *= cr0; oc[nf][1] *= cr0;
                oc[nf][2] *= cr1; oc[nf][3] *= cr1;
            }
#pragma unroll
            for (int nf = 0; nf < 8; nf++) {
                float p0 = ex2(sc[nf][0] - mn0);
                float p1 = ex2(sc[nf][1] - mn0);
                float p2 = ex2(sc[nf][2] - mn1);
                float p3 = ex2(sc[nf][3] - mn1);
                l0 += p0 + p1; l1 += p2 + p3;
                *(uint2*)&Pw[g*STRP     + nf*8 + 2*r] = make_uint2(tf32_of(p0), tf32_of(p1));
                *(uint2*)&Pw[(g+8)*STRP + nf*8 + 2*r] = make_uint2(tf32_of(p2), tf32_of(p3));
            }
            __syncwarp();
#pragma unroll
            for (int ks = 0; ks < 8; ks++) {
                unsigned pa[4];
                pa[0] = __float_as_uint(Pw[g*STRP     + ks*8 + r]);
                pa[1] = __float_as_uint(Pw[(g+8)*STRP + ks*8 + r]);
                pa[2] = __float_as_uint(Pw[g*STRP     + ks*8 + r + 4]);
                pa[3] = __float_as_uint(Pw[(g+8)*STRP + ks*8 + r + 4]);
#pragma unroll
                for (int nf = 0; nf < 16; nf++) {
                    unsigned b0 = __float_as_uint(Vs[(ks*8+r)*STRV   + nf*8 + g]);
                    unsigned b1 = __float_as_uint(Vs[(ks*8+r+4)*STRV + nf*8 + g]);
                    mma8(oc[nf], pa, b0, b1);
                }
            }
            __syncwarp();
        }
    }

    l0 += __shfl_xor_sync(0xffffffffu, l0, 1);
    l0 += __shfl_xor_sync(0xffffffffu, l0, 2);
    l1 += __shfl_xor_sync(0xffffffffu, l1, 1);
    l1 += __shfl_xor_sync(0xffffffffu, l1, 2);
    float i0 = 1.f / l0, i1 = 1.f / l1;
    float* o0 = g_ctx + ((size_t)b*S_ + qrow0 + g    ) * H_ + h*HD_;
    float* o1 = g_ctx + ((size_t)b*S_ + qrow0 + g + 8) * H_ + h*HD_;
#pragma unroll
    for (int nf = 0; nf < 16; nf++) {
        *(uint2*)&o0[nf*8 + 2*r] = make_uint2(tf32_of(oc[nf][0]*i0), tf32_of(oc[nf][1]*i0));
        *(uint2*)&o1[nf*8 + 2*r] = make_uint2(tf32_of(oc[nf][2]*i1), tf32_of(oc[nf][3]*i1));
    }
}

// ---------------- launch ---------------------------------------------------
extern "C" void kernel_launch(void* const* d_in, const int* in_sizes, int n_in,
                              void* d_out, int out_size)
{
    const float* X   = (const float*)d_in[0];
    const float* cp  = (const float*)d_in[1];
    const float* sp  = (const float*)d_in[2];
    const float* Wq  = (const float*)d_in[3];
    const float* Wk  = (const float*)d_in[4];
    const float* Wv  = (const float*)d_in[5];
    const float* Wo  = (const float*)d_in[6];
    float* out = (float*)d_out;

    cudaFuncSetAttribute(k_flash_tc, cudaFuncAttributeMaxDynamicSharedMemorySize,
                         FLASH_SMEM_BYTES);
    cudaFuncSetAttribute(k_qkv_tc, cudaFuncAttributeMaxDynamicSharedMemorySize,
                         GEMM_SMEM);
    cudaFuncSetAttribute(k_out_tc, cudaFuncAttributeMaxDynamicSharedMemorySize,
                         GEMM_SMEM);

    // one fused cvt launch: y=0 X (2M float4), y=1..4 W (1M float4 each)
    k_cvt_all<<<dim3((M_*H_/4)/256, 5), 256>>>(X, Wq, Wk, Wv, Wo);

    k_qkv_tc<<<dim3(48, M_/GM), 256, GEMM_SMEM>>>();

    int total = B_ * NH_ * S_ * 64;        // 4,194,304
    k_rope<<<total / 256, 256>>>(cp, sp);

    k_flash_tc<<<dim3(NQT, B_*NH_), 256, FLASH_SMEM_BYTES>>>();

    k_out_tc<<<dim3(H_/GN, M_/GM), 256, GEMM_SMEM>>>(out);
}

// round 14
// speedup vs baseline: 1.3460x; 1.0792x over previous
#include <cuda_runtime.h>
#include <cuda_bf16.h>
#include <cstdint>

#define B_  2
#define S_  2048
#define H_  2048
#define NH_ 16
#define HD_ 128
#define M_  (B_*S_)            // 4096
#define SCALE_ 0.08838834764831845f   // 128^-0.5
#define LOG2E_ 1.4426950408889634f

// ---------------- scratch (device globals: no allocation allowed) ----------
__device__ float g_q[(size_t)B_*NH_*S_*HD_];     // [b,h,s,d] fp32 (post-rope)
__device__ float g_k[(size_t)B_*NH_*S_*HD_];     // [b,h,s,d] tf32 bits (post-rope)
__device__ float g_v[(size_t)B_*NH_*S_*HD_];     // [b,h,s,d] tf32 bits
__device__ float g_ctx[(size_t)B_*S_*H_];        // [b,s,h*HD+d] tf32 bits
__device__ float g_xc[(size_t)M_*H_];            // X  pre-rounded to tf32
__device__ float g_wq[(size_t)H_*H_];            // W* pre-rounded to tf32
__device__ float g_wk[(size_t)H_*H_];
__device__ float g_wv[(size_t)H_*H_];
__device__ float g_wo[(size_t)H_*H_];

// ---------------- tf32 helpers ---------------------------------------------
__device__ __forceinline__ unsigned tf32_of(float f) {
    unsigned r; asm("cvt.rn.tf32.f32 %0, %1;" : "=r"(r) : "f"(f)); return r;
}
__device__ __forceinline__ uint4 cvt4(float4 v) {
    uint4 o; o.x = tf32_of(v.x); o.y = tf32_of(v.y); o.z = tf32_of(v.z); o.w = tf32_of(v.w);
    return o;
}
__device__ __forceinline__ float ex2(float x) {
    float r; asm("ex2.approx.ftz.f32 %0, %1;" : "=f"(r) : "f"(x)); return r;
}
__device__ __forceinline__ void mma8(float* c, const unsigned* a, unsigned b0, unsigned b1) {
    asm volatile(
        "mma.sync.aligned.m16n8k8.row.col.f32.tf32.tf32.f32 "
        "{%0,%1,%2,%3}, {%4,%5,%6,%7}, {%8,%9}, {%0,%1,%2,%3};"
        : "+f"(c[0]), "+f"(c[1]), "+f"(c[2]), "+f"(c[3])
        : "r"(a[0]), "r"(a[1]), "r"(a[2]), "r"(a[3]), "r"(b0), "r"(b1));
}
__device__ __forceinline__ uint32_t smem_u32(const void* p) {
    uint32_t a;
    asm("{ .reg .u64 t; cvta.to.shared.u64 t, %1; cvt.u32.u64 %0, t; }" : "=r"(a) : "l"(p));
    return a;
}
__device__ __forceinline__ void cp16(uint32_t saddr, const float* g) {
    asm volatile("cp.async.cg.shared.global [%0], [%1], 16;" :: "r"(saddr), "l"(g) : "memory");
}
#define CP_COMMIT() asm volatile("cp.async.commit_group;" ::: "memory")
#define CP_WAIT1()  asm volatile("cp.async.wait_group 1;" ::: "memory")
#define CP_WAIT0()  asm volatile("cp.async.wait_group 0;" ::: "memory")

// ---------------- pre-conversion (one launch, 5 tensors) -------------------
__global__ void k_cvt_all(const float* __restrict__ X,
                          const float* __restrict__ Wq, const float* __restrict__ Wk,
                          const float* __restrict__ Wv, const float* __restrict__ Wo) {
    int i = blockIdx.x * blockDim.x + threadIdx.x;
    int y = blockIdx.y;
    const float* src; float* dst;
    if (y == 0)      { src = X;  dst = g_xc; }
    else if (y == 1) { src = Wq; dst = g_wq; if (i >= H_*H_/4) return; }
    else if (y == 2) { src = Wk; dst = g_wk; if (i >= H_*H_/4) return; }
    else if (y == 3) { src = Wv; dst = g_wv; if (i >= H_*H_/4) return; }
    else             { src = Wo; dst = g_wo; if (i >= H_*H_/4) return; }
    float4 v = ((const float4*)src)[i];
    ((uint4*)dst)[i] = cvt4(v);
}

// ======================= tf32 mma.sync GEMM ================================
// CTA 128x128, GK=32 (128B rows, SW128 swizzle), 256 thr, 8 warps as
// 2(m)x4(n), warp tile 64x32, scalar-LDS fragments. 3 cp.async stages
// x 32KB = 96KB -> 2 CTAs/SM.
#define GM 128
#define GN 128
#define GK 32
#define NST 3
#define A_STG (GM*GK*4)                     // 16384
#define STG   (2*A_STG)                     // 32768
#define GEMM_SMEM (NST*STG)                 // 98304
#define TST 132                             // rope-tile smem stride (floats)

__device__ __forceinline__ int swz128(int row, int cb) {   // byte offset
    return row * 128 + (cb ^ ((row & 7) << 4));
}

// MODE 0: C[m*H_+n]
// MODE 2: scatter [b,h,s,d] tf32 (V)
// MODE 3: scatter [b,h,s,d] fp32 with fused RoPE (Q)
// MODE 4: scatter [b,h,s,d] tf32 with fused RoPE (K)
template<int MODE>
__device__ __forceinline__ void gemm_tc(const float* __restrict__ A,
                                        const float* __restrict__ W,
                                        float* __restrict__ Cdst,
                                        int mb, int nb,
                                        const float* __restrict__ cosp,
                                        const float* __restrict__ sinp)
{
    extern __shared__ float gsm[];
    const uint32_t sb = smem_u32(gsm);
    const int tid = threadIdx.x;
    const int wid = tid >> 5, lane = tid & 31;
    const int g = lane >> 2, r = lane & 3;
    const int wm = (wid >> 2) * 64;
    const int wn = (wid & 3) * 32;

    float c[4][4][4];
#pragma unroll
    for (int i = 0; i < 4; i++)
#pragma unroll
        for (int j = 0; j < 4; j++)
#pragma unroll
            for (int e = 0; e < 4; e++) c[i][j][e] = 0.f;

    const int lrow = tid >> 3, lseg = tid & 7;         // cp.async mapping

    auto issue = [&](int ch) {
        uint32_t st = sb + (ch % NST) * STG;
        const float* Ab = A + (size_t)mb * H_ + ch * GK;
        const float* Wb = W + (size_t)nb * H_ + ch * GK;
#pragma unroll
        for (int q = 0; q < 4; q++) {                  // A: 128 rows
            int row = lrow + 32 * q;
            cp16(st + swz128(row, lseg * 16), Ab + (size_t)row * H_ + lseg * 4);
        }
        uint32_t stb = st + A_STG;
#pragma unroll
        for (int q = 0; q < 4; q++) {                  // B: 128 rows
            int row = lrow + 32 * q;
            cp16(stb + swz128(row, lseg * 16), Wb + (size_t)row * H_ + lseg * 4);
        }
    };

    issue(0); CP_COMMIT();
    issue(1); CP_COMMIT();

    const int NCH = H_ / GK;                           // 64
    for (int ch = 0; ch < NCH; ch++) {
        CP_WAIT1();
        __syncthreads();
        if (ch + 2 < NCH) issue(ch + 2);
        CP_COMMIT();
        const char* as = (const char*)gsm + (ch % NST) * STG;
        const char* bs = as + A_STG;
#pragma unroll
        for (int ks = 0; ks < 4; ks++) {
            unsigned bf[4][2];
#pragma unroll
            for (int nf = 0; nf < 4; nf++) {
                int row = wn + nf * 8 + g;
                bf[nf][0] = *(const unsigned*)(bs + swz128(row, (ks*8 + r) * 4));
                bf[nf][1] = *(const unsigned*)(bs + swz128(row, (ks*8 + r + 4) * 4));
            }
#pragma unroll
            for (int mf = 0; mf < 4; mf++) {
                unsigned af[4];
                int row = wm + mf * 16 + g;
                af[0] = *(const unsigned*)(as + swz128(row,     (ks*8 + r) * 4));
                af[1] = *(const unsigned*)(as + swz128(row + 8, (ks*8 + r) * 4));
                af[2] = *(const unsigned*)(as + swz128(row,     (ks*8 + r + 4) * 4));
                af[3] = *(const unsigned*)(as + swz128(row + 8, (ks*8 + r + 4) * 4));
#pragma unroll
                for (int nf = 0; nf < 4; nf++)
                    mma8(c[mf][nf], af, bf[nf][0], bf[nf][1]);
            }
        }
    }

    if (MODE == 0 || MODE == 2) {
        // direct epilogue
#pragma unroll
        for (int mf = 0; mf < 4; mf++) {
#pragma unroll
            for (int nf = 0; nf < 4; nf++) {
                int mrow = mb + wm + mf * 16 + g;
                int col  = nb + wn + nf * 8 + r * 2;
#pragma unroll
                for (int half = 0; half < 2; half++) {
                    int m = mrow + half * 8;
                    float2 v = make_float2(c[mf][nf][half * 2], c[mf][nf][half * 2 + 1]);
                    if (MODE == 0) {
                        *(float2*)&Cdst[(size_t)m * H_ + col] = v;
                    } else {
                        v.x = __uint_as_float(tf32_of(v.x));
                        v.y = __uint_as_float(tf32_of(v.y));
                        int b = m >> 11, s = m & (S_ - 1);
                        int h = col >> 7, d0 = col & (HD_ - 1);
                        *(float2*)&Cdst[(((size_t)(b * NH_ + h)) * S_ + s) * HD_ + d0] = v;
                    }
                }
            }
        }
    } else {
        // fused-RoPE epilogue: stage 128x128 tile in smem, rotate (d, d+64)
        __syncthreads();                         // stage buffers dead now
        float* tile = gsm;                       // [128][TST]
#pragma unroll
        for (int mf = 0; mf < 4; mf++) {
#pragma unroll
            for (int nf = 0; nf < 4; nf++) {
                int rloc = wm + mf * 16 + g;
                int cloc = wn + nf * 8 + r * 2;
#pragma unroll
                for (int half = 0; half < 2; half++) {
                    *(float2*)&tile[(rloc + half*8)*TST + cloc] =
                        make_float2(c[mf][nf][half*2], c[mf][nf][half*2 + 1]);
                }
            }
        }
        __syncthreads();
        const int h = nb >> 7;                   // CTA covers exactly one head
#pragma unroll
        for (int i = 0; i < 32; i++) {
            int p = tid + 256 * i;               // 0..8191
            int row = p >> 6;                    // 0..127
            int d   = p & 63;                    // 0..63
            int m = mb + row;
            int b = m >> 11, s = m & (S_ - 1);
            float x1 = tile[row*TST + d];
            float x2 = tile[row*TST + d + 64];
            float c1 = cosp[s*HD_ + d],      s1 = sinp[s*HD_ + d];
            float c2 = cosp[s*HD_ + d + 64], s2 = sinp[s*HD_ + d + 64];
            float o1 = x1*c1 - x2*s1;
            float o2 = x2*c2 + x1*s2;
            size_t bp = (((size_t)(b*NH_ + h)) * S_ + s) * HD_;
            if (MODE == 3) {
                Cdst[bp + d]      = o1;
                Cdst[bp + d + 64] = o2;
            } else {
                Cdst[bp + d]      = __uint_as_float(tf32_of(o1));
                Cdst[bp + d + 64] = __uint_as_float(tf32_of(o2));
            }
        }
    }
}

__global__ void __launch_bounds__(256, 2) k_qkv_tc(const float* __restrict__ cosp,
                                                   const float* __restrict__ sinp) {
    int which = blockIdx.x >> 4;                 // 0=q 1=k 2=v
    int nb = (blockIdx.x & 15) * GN;
    int mb = blockIdx.y * GM;
    if (which == 0)      gemm_tc<3>(g_xc, g_wq, g_q, mb, nb, cosp, sinp);
    else if (which == 1) gemm_tc<4>(g_xc, g_wk, g_k, mb, nb, cosp, sinp);
    else                 gemm_tc<2>(g_xc, g_wv, g_v, mb, nb, nullptr, nullptr);
}
__global__ void __launch_bounds__(256, 2) k_out_tc(float* __restrict__ C) {
    gemm_tc<0>(g_ctx, g_wo, C, (int)blockIdx.y * GM, (int)blockIdx.x * GN,
               nullptr, nullptr);
}

// ---------------- causal flash attention (tensor cores, cp.async) ----------
#define BQ   128
#define BKT  64
#define NQT  (S_/BQ)                      // 16
#define STRK 132
#define STRV 136
#define STRP 68
#define KVW  (64*STRK + 64*STRV)          // floats per K+V buffer = 17152
#define PS_OFF (2*KVW)                    // 34304
#define FLASH_SMEM_BYTES ((PS_OFF + 8*16*STRP)*4)   // 172032

__global__ void __launch_bounds__(256, 1) k_flash_tc()
{
    extern __shared__ float fsm[];
    const uint32_t fsb = smem_u32(fsm);
    const int tid = threadIdx.x;
    const int wid = tid >> 5, lane = tid & 31;
    const int g = lane >> 2, r = lane & 3;
    // LPT schedule: heaviest q-tiles (largest qt) across all bh first
    const int qt = (NQT - 1) - ((int)blockIdx.x >> 5);
    const int bh = (int)blockIdx.x & 31;
    const int b = bh >> 4, h = bh & (NH_ - 1);
    const size_t base = (size_t)bh * S_ * HD_;
    const int qrow0 = qt*BQ + wid*16;

    unsigned qa[16][4];
    {
        const float* qp = g_q + base + (size_t)qrow0 * HD_;
        const float qs = SCALE_ * LOG2E_;           // log2-domain scores
#pragma unroll
        for (int ks = 0; ks < 16; ks++) {
            qa[ks][0] = tf32_of(qp[(size_t)g*HD_     + ks*8 + r    ] * qs);
            qa[ks][1] = tf32_of(qp[(size_t)(g+8)*HD_ + ks*8 + r    ] * qs);
            qa[ks][2] = tf32_of(qp[(size_t)g*HD_     + ks*8 + r + 4] * qs);
            qa[ks][3] = tf32_of(qp[(size_t)(g+8)*HD_ + ks*8 + r + 4] * qs);
        }
    }

    float oc[16][4];
#pragma unroll
    for (int nf = 0; nf < 16; nf++)
#pragma unroll
        for (int e = 0; e < 4; e++) oc[nf][e] = 0.f;
    float m0 = -1e30f, m1 = -1e30f, l0 = 0.f, l1 = 0.f;

    float* Pw = fsm + PS_OFF + wid * (16*STRP);
    const int ntiles = 2*(qt + 1);

    auto stage = [&](int kt2, int buf) {
        const float* kp = g_k + base + (size_t)kt2*BKT*HD_;
        const float* vp = g_v + base + (size_t)kt2*BKT*HD_;
        uint32_t ks_ = fsb + (uint32_t)buf * (KVW*4);
        uint32_t vs_ = ks_ + 64*STRK*4;
#pragma unroll
        for (int it = 0; it < 8; it++) {
            int f = tid + 256*it;            // 0..2047
            int row = f >> 5, c4 = (f & 31) * 4;
            cp16(ks_ + (row*STRK + c4)*4, kp + row*HD_ + c4);
            cp16(vs_ + (row*STRV + c4)*4, vp + row*HD_ + c4);
        }
    };

    stage(0, 0); CP_COMMIT();

    for (int kt = 0; kt < ntiles; kt++) {
        CP_WAIT0();
        __syncthreads();
        if (kt + 1 < ntiles) { stage(kt + 1, (kt + 1) & 1); CP_COMMIT(); }
        const float* Ks = fsm + (kt & 1) * KVW;
        const float* Vs = Ks + 64*STRK;

        if (kt*BKT <= qrow0 + 15) {
            float sc[8][4];
#pragma unroll
            for (int nf = 0; nf < 8; nf++)
#pragma unroll
                for (int e = 0; e < 4; e++) sc[nf][e] = 0.f;
#pragma unroll
            for (int ks = 0; ks < 16; ks++) {
#pragma unroll
                for (int nf = 0; nf < 8; nf++) {
                    unsigned b0 = __float_as_uint(Ks[(nf*8+g)*STRK + ks*8 + r]);
                    unsigned b1 = __float_as_uint(Ks[(nf*8+g)*STRK + ks*8 + r + 4]);
                    mma8(sc[nf], qa[ks], b0, b1);
                }
            }
            if (kt*BKT + BKT - 1 > qrow0) {
#pragma unroll
                for (int nf = 0; nf < 8; nf++) {
                    int key0 = kt*BKT + nf*8 + 2*r;
                    if (key0     > qrow0 + g)     sc[nf][0] = -1e30f;
                    if (key0 + 1 > qrow0 + g)     sc[nf][1] = -1e30f;
                    if (key0     > qrow0 + g + 8) sc[nf][2] = -1e30f;
                    if (key0 + 1 > qrow0 + g + 8) sc[nf][3] = -1e30f;
                }
            }
            float mx0 = sc[0][0], mx1 = sc[0][2];
#pragma unroll
            for (int nf = 0; nf < 8; nf++) {
                mx0 = fmaxf(mx0, fmaxf(sc[nf][0], sc[nf][1]));
                mx1 = fmaxf(mx1, fmaxf(sc[nf][2], sc[nf][3]));
            }
            mx0 = fmaxf(mx0, __shfl_xor_sync(0xffffffffu, mx0, 1));
            mx0 = fmaxf(mx0, __shfl_xor_sync(0xffffffffu, mx0, 2));
            mx1 = fmaxf(mx1, __shfl_xor_sync(0xffffffffu, mx1, 1));
            mx1 = fmaxf(mx1, __shfl_xor_sync(0xffffffffu, mx1, 2));
            float mn0 = fmaxf(m0, mx0), mn1 = fmaxf(m1, mx1);
            float cr0 = ex2(m0 - mn0), cr1 = ex2(m1 - mn1);
            m0 = mn0; m1 = mn1;
            l0 *= cr0; l1 *= cr1;
#pragma unroll
            for (int nf = 0; nf < 16; nf++) {
                oc[nf][0] *= cr0; oc[nf][1] *= cr0;
                oc[nf][2] *= cr1; oc[nf][3] *= cr1;
            }
#pragma unroll
            for (int nf = 0; nf < 8; nf++) {
                float p0 = ex2(sc[nf][0] - mn0);
                float p1 = ex2(sc[nf][1] - mn0);
                float p2 = ex2(sc[nf][2] - mn1);
                float p3 = ex2(sc[nf][3] - mn1);
                l0 += p0 + p1; l1 += p2 + p3;
                *(uint2*)&Pw[g*STRP     + nf*8 + 2*r] = make_uint2(tf32_of(p0), tf32_of(p1));
                *(uint2*)&Pw[(g+8)*STRP + nf*8 + 2*r] = make_uint2(tf32_of(p2), tf32_of(p3));
            }
            __syncwarp();
#pragma unroll
            for (int ks = 0; ks < 8; ks++) {
                unsigned pa[4];
                pa[0] = __float_as_uint(Pw[g*STRP     + ks*8 + r]);
                pa[1] = __float_as_uint(Pw[(g+8)*STRP + ks*8 + r]);
                pa[2] = __float_as_uint(Pw[g*STRP     + ks*8 + r + 4]);
                pa[3] = __float_as_uint(Pw[(g+8)*STRP + ks*8 + r + 4]);
#pragma unroll
                for (int nf = 0; nf < 16; nf++) {
                    unsigned b0 = __float_as_uint(Vs[(ks*8+r)*STRV   + nf*8 + g]);
                    unsigned b1 = __float_as_uint(Vs[(ks*8+r+4)*STRV + nf*8 + g]);
                    mma8(oc[nf], pa, b0, b1);
                }
            }
            __syncwarp();
        }
    }

    l0 += __shfl_xor_sync(0xffffffffu, l0, 1);
    l0 += __shfl_xor_sync(0xffffffffu, l0, 2);
    l1 += __shfl_xor_sync(0xffffffffu, l1, 1);
    l1 += __shfl_xor_sync(0xffffffffu, l1, 2);
    float i0 = 1.f / l0, i1 = 1.f / l1;
    float* o0 = g_ctx + ((size_t)b*S_ + qrow0 + g    ) * H_ + h*HD_;
    float* o1 = g_ctx + ((size_t)b*S_ + qrow0 + g + 8) * H_ + h*HD_;
#pragma unroll
    for (int nf = 0; nf < 16; nf++) {
        *(uint2*)&o0[nf*8 + 2*r] = make_uint2(tf32_of(oc[nf][0]*i0), tf32_of(oc[nf][1]*i0));
        *(uint2*)&o1[nf*8 + 2*r] = make_uint2(tf32_of(oc[nf][2]*i1), tf32_of(oc[nf][3]*i1));
    }
}

// ---------------- launch ---------------------------------------------------
extern "C" void kernel_launch(void* const* d_in, const int* in_sizes, int n_in,
                              void* d_out, int out_size)
{
    const float* X   = (const float*)d_in[0];
    const float* cp  = (const float*)d_in[1];
    const float* sp  = (const float*)d_in[2];
    const float* Wq  = (const float*)d_in[3];
    const float* Wk  = (const float*)d_in[4];
    const float* Wv  = (const float*)d_in[5];
    const float* Wo  = (const float*)d_in[6];
    float* out = (float*)d_out;

    cudaFuncSetAttribute(k_flash_tc, cudaFuncAttributeMaxDynamicSharedMemorySize,
                         FLASH_SMEM_BYTES);
    cudaFuncSetAttribute(k_qkv_tc, cudaFuncAttributeMaxDynamicSharedMemorySize,
                         GEMM_SMEM);
    cudaFuncSetAttribute(k_out_tc, cudaFuncAttributeMaxDynamicSharedMemorySize,
                         GEMM_SMEM);

    // fused cvt: y=0 X (2M float4), y=1..4 W (1M float4 each)
    k_cvt_all<<<dim3((M_*H_/4)/256, 5), 256>>>(X, Wq, Wk, Wv, Wo);

    // QKV GEMM with fused RoPE in Q/K epilogues
    k_qkv_tc<<<dim3(48, M_/GM), 256, GEMM_SMEM>>>(cp, sp);

    // flash: LPT-ordered 1D grid (512 = 16 qt x 32 bh)
    k_flash_tc<<<NQT * B_ * NH_, 256, FLASH_SMEM_BYTES>>>();

    k_out_tc<<<dim3(H_/GN, M_/GM), 256, GEMM_SMEM>>>(out);
}

// round 16
// speedup vs baseline: 2.2707x; 1.6870x over previous
#include <cuda_runtime.h>
#include <cuda_fp16.h>
#include <cstdint>

#define B_  2
#define S_  2048
#define H_  2048
#define NH_ 16
#define HD_ 128
#define M_  (B_*S_)            // 4096
#define SCALE_ 0.08838834764831845f   // 128^-0.5
#define LOG2E_ 1.4426950408889634f

// ---------------- scratch (device globals: no allocation allowed) ----------
__device__ float  g_q[(size_t)B_*NH_*S_*HD_];    // [b,h,s,d] fp32 (post-rope)
__device__ __half g_k[(size_t)B_*NH_*S_*HD_];    // [b,h,s,d] fp16 (post-rope)
__device__ float  g_v[(size_t)B_*NH_*S_*HD_];    // [b,h,s,d] tf32 bits
__device__ __half g_ctx[(size_t)B_*S_*H_];       // [b,s,h*HD+d] fp16
__device__ __half g_xc[(size_t)M_*H_];           // X  fp16
__device__ __half g_wq[(size_t)H_*H_];           // W* fp16
__device__ __half g_wk[(size_t)H_*H_];
__device__ __half g_wv[(size_t)H_*H_];
__device__ __half g_wo[(size_t)H_*H_];

// ---------------- helpers ---------------------------------------------------
__device__ __forceinline__ unsigned tf32_of(float f) {
    unsigned r; asm("cvt.rn.tf32.f32 %0, %1;" : "=r"(r) : "f"(f)); return r;
}
__device__ __forceinline__ unsigned h2pack(float x, float y) {
    __half2 h = __floats2half2_rn(x, y);
    return *(unsigned*)&h;
}
__device__ __forceinline__ float ex2(float x) {
    float r; asm("ex2.approx.ftz.f32 %0, %1;" : "=f"(r) : "f"(x)); return r;
}
// tf32 m16n8k8 (used for PV in flash)
__device__ __forceinline__ void mma8(float* c, const unsigned* a, unsigned b0, unsigned b1) {
    asm volatile(
        "mma.sync.aligned.m16n8k8.row.col.f32.tf32.tf32.f32 "
        "{%0,%1,%2,%3}, {%4,%5,%6,%7}, {%8,%9}, {%0,%1,%2,%3};"
        : "+f"(c[0]), "+f"(c[1]), "+f"(c[2]), "+f"(c[3])
        : "r"(a[0]), "r"(a[1]), "r"(a[2]), "r"(a[3]), "r"(b0), "r"(b1));
}
// fp16 m16n8k16 (GEMMs + flash QK)
__device__ __forceinline__ void mma16h(float* c, const unsigned* a, unsigned b0, unsigned b1) {
    asm volatile(
        "mma.sync.aligned.m16n8k16.row.col.f32.f16.f16.f32 "
        "{%0,%1,%2,%3}, {%4,%5,%6,%7}, {%8,%9}, {%0,%1,%2,%3};"
        : "+f"(c[0]), "+f"(c[1]), "+f"(c[2]), "+f"(c[3])
        : "r"(a[0]), "r"(a[1]), "r"(a[2]), "r"(a[3]), "r"(b0), "r"(b1));
}
__device__ __forceinline__ uint32_t smem_u32(const void* p) {
    uint32_t a;
    asm("{ .reg .u64 t; cvta.to.shared.u64 t, %1; cvt.u32.u64 %0, t; }" : "=r"(a) : "l"(p));
    return a;
}
__device__ __forceinline__ void cp16(uint32_t saddr, const void* g) {
    asm volatile("cp.async.cg.shared.global [%0], [%1], 16;" :: "r"(saddr), "l"(g) : "memory");
}
#define CP_COMMIT() asm volatile("cp.async.commit_group;" ::: "memory")
#define CP_WAIT1()  asm volatile("cp.async.wait_group 1;" ::: "memory")
#define CP_WAIT0()  asm volatile("cp.async.wait_group 0;" ::: "memory")

// ---------------- pre-conversion to fp16 (one launch, 5 tensors) -----------
__global__ void k_cvt_all(const float* __restrict__ X,
                          const float* __restrict__ Wq, const float* __restrict__ Wk,
                          const float* __restrict__ Wv, const float* __restrict__ Wo) {
    int i = blockIdx.x * blockDim.x + threadIdx.x;
    int y = blockIdx.y;
    const float* src; __half* dst;
    if (y == 0)      { src = X;  dst = g_xc; }
    else if (y == 1) { src = Wq; dst = g_wq; if (i >= H_*H_/4) return; }
    else if (y == 2) { src = Wk; dst = g_wk; if (i >= H_*H_/4) return; }
    else if (y == 3) { src = Wv; dst = g_wv; if (i >= H_*H_/4) return; }
    else             { src = Wo; dst = g_wo; if (i >= H_*H_/4) return; }
    float4 v = ((const float4*)src)[i];
    uint2 o; o.x = h2pack(v.x, v.y); o.y = h2pack(v.z, v.w);
    ((uint2*)dst)[i] = o;
}

// ======================= fp16 mma.sync GEMM ================================
// CTA 128x128, GK=64 halves (128B rows, SW128 swizzle), 256 thr, 8 warps as
// 2(m)x4(n), warp tile 64x32, scalar-LDS fragments (byte pattern identical to
// the proven tf32 version). 3 cp.async stages x 32KB = 96KB -> 2 CTAs/SM.
#define GM 128
#define GN 128
#define GK 64
#define NST 3
#define A_STG (GM*GK*2)                     // 16384 B
#define STG   (2*A_STG)                     // 32768 B
#define GEMM_SMEM (NST*STG)                 // 98304
#define TST 132                             // rope-tile smem stride (floats)

__device__ __forceinline__ int swz128(int row, int cb) {   // byte offset
    return row * 128 + (cb ^ ((row & 7) << 4));
}

// MODE 0: fp32 C[m*H_+n]
// MODE 2: scatter [b,h,s,d] tf32 floats (V)
// MODE 3: scatter [b,h,s,d] fp32 with fused RoPE (Q)
// MODE 4: scatter [b,h,s,d] fp16 with fused RoPE (K)
template<int MODE>
__device__ __forceinline__ void gemm_tc(const __half* __restrict__ A,
                                        const __half* __restrict__ W,
                                        void* __restrict__ Cv,
                                        int mb, int nb,
                                        const float* __restrict__ cosp,
                                        const float* __restrict__ sinp)
{
    extern __shared__ float gsm[];
    const uint32_t sb = smem_u32(gsm);
    const int tid = threadIdx.x;
    const int wid = tid >> 5, lane = tid & 31;
    const int g = lane >> 2, r = lane & 3;
    const int wm = (wid >> 2) * 64;
    const int wn = (wid & 3) * 32;

    float c[4][4][4];
#pragma unroll
    for (int i = 0; i < 4; i++)
#pragma unroll
        for (int j = 0; j < 4; j++)
#pragma unroll
            for (int e = 0; e < 4; e++) c[i][j][e] = 0.f;

    const int lrow = tid >> 3, lseg = tid & 7;         // cp.async mapping

    auto issue = [&](int ch) {
        uint32_t st = sb + (ch % NST) * STG;
        const __half* Ab = A + (size_t)mb * H_ + ch * GK;
        const __half* Wb = W + (size_t)nb * H_ + ch * GK;
#pragma unroll
        for (int q = 0; q < 4; q++) {                  // A: 128 rows x 128B
            int row = lrow + 32 * q;
            cp16(st + swz128(row, lseg * 16), Ab + (size_t)row * H_ + lseg * 8);
        }
        uint32_t stb = st + A_STG;
#pragma unroll
        for (int q = 0; q < 4; q++) {                  // B: 128 rows x 128B
            int row = lrow + 32 * q;
            cp16(stb + swz128(row, lseg * 16), Wb + (size_t)row * H_ + lseg * 8);
        }
    };

    issue(0); CP_COMMIT();
    issue(1); CP_COMMIT();

    const int NCH = H_ / GK;                           // 32
    for (int ch = 0; ch < NCH; ch++) {
        CP_WAIT1();
        __syncthreads();
        if (ch + 2 < NCH) issue(ch + 2);
        CP_COMMIT();
        const char* as = (const char*)gsm + (ch % NST) * STG;
        const char* bs = as + A_STG;
#pragma unroll
        for (int ks = 0; ks < 4; ks++) {               // 4 x k16 = 64
            unsigned bf[4][2];
#pragma unroll
            for (int nf = 0; nf < 4; nf++) {
                int row = wn + nf * 8 + g;
                bf[nf][0] = *(const unsigned*)(bs + swz128(row, ks*32 + r*4));
                bf[nf][1] = *(const unsigned*)(bs + swz128(row, ks*32 + r*4 + 16));
            }
#pragma unroll
            for (int mf = 0; mf < 4; mf++) {
                unsigned af[4];
                int row = wm + mf * 16 + g;
                af[0] = *(const unsigned*)(as + swz128(row,     ks*32 + r*4));
                af[1] = *(const unsigned*)(as + swz128(row + 8, ks*32 + r*4));
                af[2] = *(const unsigned*)(as + swz128(row,     ks*32 + r*4 + 16));
                af[3] = *(const unsigned*)(as + swz128(row + 8, ks*32 + r*4 + 16));
#pragma unroll
                for (int nf = 0; nf < 4; nf++)
                    mma16h(c[mf][nf], af, bf[nf][0], bf[nf][1]);
            }
        }
    }

    if (MODE == 0 || MODE == 2) {
        float* Cdst = (float*)Cv;
#pragma unroll
        for (int mf = 0; mf < 4; mf++) {
#pragma unroll
            for (int nf = 0; nf < 4; nf++) {
                int mrow = mb + wm + mf * 16 + g;
                int col  = nb + wn + nf * 8 + r * 2;
#pragma unroll
                for (int half_ = 0; half_ < 2; half_++) {
                    int m = mrow + half_ * 8;
                    float2 v = make_float2(c[mf][nf][half_*2], c[mf][nf][half_*2 + 1]);
                    if (MODE == 0) {
                        *(float2*)&Cdst[(size_t)m * H_ + col] = v;
                    } else {
                        v.x = __uint_as_float(tf32_of(v.x));
                        v.y = __uint_as_float(tf32_of(v.y));
                        int b = m >> 11, s = m & (S_ - 1);
                        int h = col >> 7, d0 = col & (HD_ - 1);
                        *(float2*)&Cdst[(((size_t)(b * NH_ + h)) * S_ + s) * HD_ + d0] = v;
                    }
                }
            }
        }
    } else {
        // fused-RoPE epilogue: stage 128x128 fp32 tile in smem, rotate (d, d+64)
        __syncthreads();                         // stage buffers dead now
        float* tile = gsm;                       // [128][TST] = 67.6KB < 96KB
#pragma unroll
        for (int mf = 0; mf < 4; mf++) {
#pragma unroll
            for (int nf = 0; nf < 4; nf++) {
                int rloc = wm + mf * 16 + g;
                int cloc = wn + nf * 8 + r * 2;
#pragma unroll
                for (int half_ = 0; half_ < 2; half_++) {
                    *(float2*)&tile[(rloc + half_*8)*TST + cloc] =
                        make_float2(c[mf][nf][half_*2], c[mf][nf][half_*2 + 1]);
                }
            }
        }
        __syncthreads();
        const int h = nb >> 7;                   // CTA covers exactly one head
#pragma unroll
        for (int i = 0; i < 32; i++) {
            int p = tid + 256 * i;               // 0..8191
            int row = p >> 6;                    // 0..127
            int d   = p & 63;                    // 0..63
            int m = mb + row;
            int b = m >> 11, s = m & (S_ - 1);
            float x1 = tile[row*TST + d];
            float x2 = tile[row*TST + d + 64];
            float c1 = cosp[s*HD_ + d],      s1 = sinp[s*HD_ + d];
            float c2 = cosp[s*HD_ + d + 64], s2 = sinp[s*HD_ + d + 64];
            float o1 = x1*c1 - x2*s1;
            float o2 = x2*c2 + x1*s2;
            size_t bp = (((size_t)(b*NH_ + h)) * S_ + s) * HD_;
            if (MODE == 3) {
                float* Cf = (float*)Cv;
                Cf[bp + d]      = o1;
                Cf[bp + d + 64] = o2;
            } else {
                __half* Ch = (__half*)Cv;
                Ch[bp + d]      = __float2half_rn(o1);
                Ch[bp + d + 64] = __float2half_rn(o2);
            }
        }
    }
}

__global__ void __launch_bounds__(256, 2) k_qkv_tc(const float* __restrict__ cosp,
                                                   const float* __restrict__ sinp) {
    int which = blockIdx.x >> 4;                 // 0=q 1=k 2=v
    int nb = (blockIdx.x & 15) * GN;
    int mb = blockIdx.y * GM;
    if (which == 0)      gemm_tc<3>(g_xc, g_wq, (void*)g_q, mb, nb, cosp, sinp);
    else if (which == 1) gemm_tc<4>(g_xc, g_wk, (void*)g_k, mb, nb, cosp, sinp);
    else                 gemm_tc<2>(g_xc, g_wv, (void*)g_v, mb, nb, nullptr, nullptr);
}
__global__ void __launch_bounds__(256, 2) k_out_tc(float* __restrict__ C) {
    gemm_tc<0>(g_ctx, g_wo, (void*)C, (int)blockIdx.y * GM, (int)blockIdx.x * GN,
               nullptr, nullptr);
}

// ---------------- causal flash attention --------------------------------
// QK: fp16 m16n8k16 (K fp16 in smem, 272B rows -> conflict-free).
// PV: tf32 m16n8k8 (V fp32 tf32-bits, as before). K/V double-buffered cp.async.
#define BQ   128
#define BKT  64
#define NQT  (S_/BQ)                      // 16
#define KSTR 136                          // K row stride in halves (272B)
#define KBUF_B (64*KSTR*2)                // 17408
#define VSTR 136                          // V row stride in floats (544B)
#define VBUF_B (64*VSTR*4)                // 34816
#define BUF_B (KBUF_B + VBUF_B)           // 52224 per stage
#define PS_OFF_B (2*BUF_B)                // 104448
#define STRP 68
#define FLASH_SMEM_BYTES (PS_OFF_B + 8*16*STRP*4)   // 139264

__global__ void __launch_bounds__(256, 1) k_flash_tc()
{
    extern __shared__ float fsm[];
    const uint32_t fsb = smem_u32(fsm);
    const int tid = threadIdx.x;
    const int wid = tid >> 5, lane = tid & 31;
    const int g = lane >> 2, r = lane & 3;
    // LPT schedule: heaviest q-tiles first
    const int qt = (NQT - 1) - ((int)blockIdx.x >> 5);
    const int bh = (int)blockIdx.x & 31;
    const int b = bh >> 4, h = bh & (NH_ - 1);
    const size_t base = (size_t)bh * S_ * HD_;
    const int qrow0 = qt*BQ + wid*16;

    // Q fragments: fp16, scaled by SCALE*log2e
    unsigned qa[8][4];
    {
        const float* qp = g_q + base + (size_t)qrow0 * HD_;
        const float qs = SCALE_ * LOG2E_;
#pragma unroll
        for (int ks = 0; ks < 8; ks++) {
            float2 lo0 = *(const float2*)&qp[(size_t)g*HD_     + ks*16 + 2*r];
            float2 lo1 = *(const float2*)&qp[(size_t)(g+8)*HD_ + ks*16 + 2*r];
            float2 hi0 = *(const float2*)&qp[(size_t)g*HD_     + ks*16 + 2*r + 8];
            float2 hi1 = *(const float2*)&qp[(size_t)(g+8)*HD_ + ks*16 + 2*r + 8];
            qa[ks][0] = h2pack(lo0.x*qs, lo0.y*qs);
            qa[ks][1] = h2pack(lo1.x*qs, lo1.y*qs);
            qa[ks][2] = h2pack(hi0.x*qs, hi0.y*qs);
            qa[ks][3] = h2pack(hi1.x*qs, hi1.y*qs);
        }
    }

    float oc[16][4];
#pragma unroll
    for (int nf = 0; nf < 16; nf++)
#pragma unroll
        for (int e = 0; e < 4; e++) oc[nf][e] = 0.f;
    float m0 = -1e30f, m1 = -1e30f, l0 = 0.f, l1 = 0.f;

    float* Pw = (float*)((char*)fsm + PS_OFF_B) + wid * (16*STRP);
    const int ntiles = 2*(qt + 1);

    auto stage = [&](int kt2, int buf) {
        const __half* kp = g_k + base + (size_t)kt2*BKT*HD_;
        const float*  vp = g_v + base + (size_t)kt2*BKT*HD_;
        uint32_t kb = fsb + (uint32_t)buf * BUF_B;
        uint32_t vb = kb + KBUF_B;
#pragma unroll
        for (int it = 0; it < 4; it++) {             // K: 64 rows x 256B
            int f = tid + 256*it;                    // 0..1023
            int row = f >> 4, seg = f & 15;
            cp16(kb + row*(KSTR*2) + seg*16, kp + (size_t)row*HD_ + seg*8);
        }
#pragma unroll
        for (int it = 0; it < 8; it++) {             // V: 64 rows x 512B
            int f = tid + 256*it;                    // 0..2047
            int row = f >> 5, seg = f & 31;
            cp16(vb + row*(VSTR*4) + seg*16, vp + (size_t)row*HD_ + seg*4);
        }
    };

    stage(0, 0); CP_COMMIT();

    for (int kt = 0; kt < ntiles; kt++) {
        CP_WAIT0();
        __syncthreads();
        if (kt + 1 < ntiles) { stage(kt + 1, (kt + 1) & 1); CP_COMMIT(); }
        const __half* Ks = (const __half*)((char*)fsm + (kt & 1) * BUF_B);
        const float*  Vs = (const float*)((char*)fsm + (kt & 1) * BUF_B + KBUF_B);

        if (kt*BKT <= qrow0 + 15) {
            float sc[8][4];
#pragma unroll
            for (int nf = 0; nf < 8; nf++)
#pragma unroll
                for (int e = 0; e < 4; e++) sc[nf][e] = 0.f;
#pragma unroll
            for (int ks = 0; ks < 8; ks++) {          // 8 x k16 = 128
#pragma unroll
                for (int nf = 0; nf < 8; nf++) {
                    unsigned b0 = *(const unsigned*)&Ks[(nf*8+g)*KSTR + ks*16 + 2*r];
                    unsigned b1 = *(const unsigned*)&Ks[(nf*8+g)*KSTR + ks*16 + 2*r + 8];
                    mma16h(sc[nf], qa[ks], b0, b1);
                }
            }
            if (kt*BKT + BKT - 1 > qrow0) {
#pragma unroll
                for (int nf = 0; nf < 8; nf++) {
                    int key0 = kt*BKT + nf*8 + 2*r;
                    if (key0     > qrow0 + g)     sc[nf][0] = -1e30f;
                    if (key0 + 1 > qrow0 + g)     sc[nf][1] = -1e30f;
                    if (key0     > qrow0 + g + 8) sc[nf][2] = -1e30f;
                    if (key0 + 1 > qrow0 + g + 8) sc[nf][3] = -1e30f;
                }
            }
            float mx0 = sc[0][0], mx1 = sc[0][2];
#pragma unroll
            for (int nf = 0; nf < 8; nf++) {
                mx0 = fmaxf(mx0, fmaxf(sc[nf][0], sc[nf][1]));
                mx1 = fmaxf(mx1, fmaxf(sc[nf][2], sc[nf][3]));
            }
            mx0 = fmaxf(mx0, __shfl_xor_sync(0xffffffffu, mx0, 1));
            mx0 = fmaxf(mx0, __shfl_xor_sync(0xffffffffu, mx0, 2));
            mx1 = fmaxf(mx1, __shfl_xor_sync(0xffffffffu, mx1, 1));
            mx1 = fmaxf(mx1, __shfl_xor_sync(0xffffffffu, mx1, 2));
            float mn0 = fmaxf(m0, mx0), mn1 = fmaxf(m1, mx1);
            float cr0 = ex2(m0 - mn0), cr1 = ex2(m1 - mn1);
            m0 = mn0; m1 = mn1;
            l0 *= cr0; l1 *= cr1;
#pragma unroll
            for (int nf = 0; nf < 16; nf++) {
                oc[nf][0] *= cr0; oc[nf][1] *= cr0;
                oc[nf][2] *= cr1; oc[nf][3] *= cr1;
            }
#pragma unroll
            for (int nf = 0; nf < 8; nf++) {
                float p0 = ex2(sc[nf][0] - mn0);
                float p1 = ex2(sc[nf][1] - mn0);
                float p2 = ex2(sc[nf][2] - mn1);
                float p3 = ex2(sc[nf][3] - mn1);
                l0 += p0 + p1; l1 += p2 + p3;
                *(uint2*)&Pw[g*STRP     + nf*8 + 2*r] = make_uint2(tf32_of(p0), tf32_of(p1));
                *(uint2*)&Pw[(g+8)*STRP + nf*8 + 2*r] = make_uint2(tf32_of(p2), tf32_of(p3));
            }
            __syncwarp();
#pragma unroll
            for (int ks = 0; ks < 8; ks++) {          // PV: tf32 k8
                unsigned pa[4];
                pa[0] = __float_as_uint(Pw[g*STRP     + ks*8 + r]);
                pa[1] = __float_as_uint(Pw[(g+8)*STRP + ks*8 + r]);
                pa[2] = __float_as_uint(Pw[g*STRP     + ks*8 + r + 4]);
                pa[3] = __float_as_uint(Pw[(g+8)*STRP + ks*8 + r + 4]);
#pragma unroll
                for (int nf = 0; nf < 16; nf++) {
                    unsigned b0 = __float_as_uint(Vs[(ks*8+r)*VSTR   + nf*8 + g]);
                    unsigned b1 = __float_as_uint(Vs[(ks*8+r+4)*VSTR + nf*8 + g]);
                    mma8(oc[nf], pa, b0, b1);
                }
            }
            __syncwarp();
        }
    }

    l0 += __shfl_xor_sync(0xffffffffu, l0, 1);
    l0 += __shfl_xor_sync(0xffffffffu, l0, 2);
    l1 += __shfl_xor_sync(0xffffffffu, l1, 1);
    l1 += __shfl_xor_sync(0xffffffffu, l1, 2);
    float i0 = 1.f / l0, i1 = 1.f / l1;
    __half* o0 = g_ctx + ((size_t)b*S_ + qrow0 + g    ) * H_ + h*HD_;
    __half* o1 = g_ctx + ((size_t)b*S_ + qrow0 + g + 8) * H_ + h*HD_;
#pragma unroll
    for (int nf = 0; nf < 16; nf++) {
        *(__half2*)&o0[nf*8 + 2*r] = __floats2half2_rn(oc[nf][0]*i0, oc[nf][1]*i0);
        *(__half2*)&o1[nf*8 + 2*r] = __floats2half2_rn(oc[nf][2]*i1, oc[nf][3]*i1);
    }
}

// ---------------- launch ---------------------------------------------------
extern "C" void kernel_launch(void* const* d_in, const int* in_sizes, int n_in,
                              void* d_out, int out_size)
{
    const float* X   = (const float*)d_in[0];
    const float* cp  = (const float*)d_in[1];
    const float* sp  = (const float*)d_in[2];
    const float* Wq  = (const float*)d_in[3];
    const float* Wk  = (const float*)d_in[4];
    const float* Wv  = (const float*)d_in[5];
    const float* Wo  = (const float*)d_in[6];
    float* out = (float*)d_out;

    cudaFuncSetAttribute(k_flash_tc, cudaFuncAttributeMaxDynamicSharedMemorySize,
                         FLASH_SMEM_BYTES);
    cudaFuncSetAttribute(k_qkv_tc, cudaFuncAttributeMaxDynamicSharedMemorySize,
                         GEMM_SMEM);
    cudaFuncSetAttribute(k_out_tc, cudaFuncAttributeMaxDynamicSharedMemorySize,
                         GEMM_SMEM);

    // fused cvt to fp16: y=0 X (2M float4), y=1..4 W (1M float4 each)
    k_cvt_all<<<dim3((M_*H_/4)/256, 5), 256>>>(X, Wq, Wk, Wv, Wo);

    // QKV GEMM (fp16) with fused RoPE in Q/K epilogues
    k_qkv_tc<<<dim3(48, M_/GM), 256, GEMM_SMEM>>>(cp, sp);

    // flash: LPT-ordered 1D grid (512 = 16 qt x 32 bh)
    k_flash_tc<<<NQT * B_ * NH_, 256, FLASH_SMEM_BYTES>>>();

    k_out_tc<<<dim3(H_/GN, M_/GM), 256, GEMM_SMEM>>>(out);
}